// round 11
// baseline (speedup 1.0000x reference)
#include <cuda_runtime.h>
#include <math.h>
#include <stddef.h>

// ---------------------------------------------------------------------------
// AttnDecoderRNN2 single step, algebraically reduced (validated):
//  * attention window always t in [0,9]; softmax max cancels in L1 norm
//  * zero LSTM state -> Whh unused, f-gate dead (i,g,o rows only: J=3072)
// Round 10: pipe-balanced inner loop. 256 thr, 8m x 4j per thread, X stored
// DUPLICATED (broadcast LDS, 1 cyc) so per kk: 4 bcast + 1 W LDS.128 + 16
// FMA2, no MOVs. Crossbar/slice = fma floor = 1024 cyc; issue 672/SMSP.
// Round-5 stage structure (7 barriers), monotonic 2-level barrier.
// ---------------------------------------------------------------------------

#define GRID    148
#define NTHR    256
#define N_B     64
#define T_ENC   2000
#define ENC     512
#define ATT     256
#define H4      1024
#define G3      3072
#define IN_LSTM 832
#define DECCAT  1536
#define NWIN    10
#define OUT_J   160

#define S_ATT 6
#define S_SP2 4
#define S_P2  8
#define S_L   6
#define S_OUT 32
#define NSUB  16

typedef unsigned long long u64;

// scratch (device globals; allocation forbidden)
__device__ __align__(16) float g_att_parts[S_ATT * 640 * ATT];
__device__ __align__(16) float g_p1_parts [2 * N_B * 512];
__device__ __align__(16) float g_sp2_parts[S_SP2 * N_B * 512];
__device__ __align__(16) float g_p2_parts [S_P2 * N_B * 256];
__device__ __align__(16) float g_sb       [N_B * ATT];
__device__ __align__(16) float g_lstm_parts[S_L * N_B * G3];
__device__ __align__(16) float g_out_parts[S_OUT * N_B * OUT_J];
__device__ __align__(16) float g_inlstm   [N_B * IN_LSTM];
__device__ __align__(16) float g_h1       [N_B * H4];
__device__ __align__(16) float g_dec      [N_B * DECCAT];    // [h2 | context]

// monotonic two-level grid barrier
__device__ unsigned g_cnt_sub[NSUB * 32];   // padded 128B apart
__device__ unsigned g_cnt_top = 0;
__device__ volatile unsigned g_sense = 0;

struct Ptrs {
    const float *input_enc, *input_dec, *spkr, *speed;
    const float *W_enc, *b_enc, *W_spkr, *conv_prev, *W_speed_att, *W_proj, *b_proj;
    const float *W_sp1, *b_sp1, *W_sp2, *b_sp2;
    const float *W_p1, *b_p1, *W_p2, *b_p2;
    const float *Wih0, *bih0, *bhh0, *Wih1, *bih1, *bhh1, *W_out, *b_out;
    const int *lengths;
    float *out, *ctx_out;
    int write_ctx;
};

__device__ __forceinline__ float sigm(float x) { return 1.f / (1.f + expf(-x)); }

#define FMA2(d, a, b) asm("fma.rn.f32x2 %0,%1,%2,%0;" : "+l"(d) : "l"(a), "l"(b))
#define UNPK(lo, hi, v) asm("mov.b64 {%0,%1},%2;" : "=f"(lo), "=f"(hi) : "l"(v))

enum { M_ATT = 0, M_P1, M_SP2, M_SB, M_P2, M_L0, M_L1, M_OUT };

// ---------------------------------------------------------------------------
__device__ __forceinline__ void gbar(unsigned target)
{
    __syncthreads();
    if (threadIdx.x == 0) {
        __threadfence();
        unsigned sub = blockIdx.x & (NSUB - 1);
        unsigned subcnt = (GRID / NSUB) + ((sub < (GRID & (NSUB - 1))) ? 1u : 0u);
        if (atomicAdd(&g_cnt_sub[sub * 32], 1u) == target * subcnt - 1u) {
            if (atomicAdd(&g_cnt_top, 1u) == target * NSUB - 1u) {
                __threadfence();
                g_sense = target;
            }
        }
        while (g_sense < target) __nanosleep(20);
        __threadfence();
    }
    __syncthreads();
}

// ---------------------------------------------------------------------------
// double-buffered GEMM tile, 256 threads. Tile 64m x 128j x chunk-k.
// X duplicated in smem: Xs[kk][2m]=Xs[kk][2m+1]=x(m). Per-thread 8m x 4j.
// Inner per kk: 4 broadcast LDS.128 (X) + 1 LDS.128 (W) + 16 FMA2.
// ---------------------------------------------------------------------------
__device__ __noinline__ void gemm_tile(int mode, int jt, int s, int mt,
                                       const Ptrs& P,
                                       float (*Xs)[16][136], float (*Ws)[16][132])
{
    int K, chunk, J;
    const float* W;
    switch (mode) {
        case M_ATT: K = 512;  chunk = 96;  J = 256;   W = P.W_enc;  break;
        case M_P1:  K = 144;  chunk = 80;  J = 512;   W = P.W_p1;   break;
        case M_SP2: K = 256;  chunk = 64;  J = 512;   W = P.W_sp2;  break;
        case M_SB:  K = 64;   chunk = 64;  J = 256;   W = P.W_spkr; break;
        case M_P2:  K = 512;  chunk = 64;  J = 256;   W = P.W_p2;   break;
        case M_L0:  K = 832;  chunk = 144; J = G3;    W = P.Wih0;   break;
        case M_L1:  K = 1024; chunk = 176; J = G3;    W = P.Wih1;   break;
        default:    K = 1536; chunk = 48;  J = OUT_J; W = P.W_out;  break;
    }
    int lstm = (mode == M_L0 || mode == M_L1);
    int j0 = jt * 128, m0 = mt * 64;
    int kbeg = s * chunk;
    int kend = min(K, kbeg + chunk);
    int nsl  = (kend - kbeg) >> 4;

    int tid  = threadIdx.x;
    int mrow = tid >> 2;          // 0..63
    int kc   = (tid & 3) * 4;
    int mg   = m0 + mrow;

    const float* xrow = 0; float spd = 0.f;
    switch (mode) {
        case M_ATT: { int n = mg / 10; int t = mg - n * 10;
                      xrow = P.input_enc + ((size_t)n * T_ENC + t) * ENC; } break;
        case M_P1:  xrow = P.input_dec + mg * 80; break;
        case M_SP2: spd = P.speed[mg]; break;
        case M_SB:  xrow = P.spkr + mg * 64; break;
        case M_P2:  break;   // from p1 partials
        case M_L0:  xrow = g_inlstm + mg * IN_LSTM; break;
        case M_L1:  xrow = g_h1 + (size_t)mg * H4; break;
        default:    xrow = g_dec + (size_t)mg * DECCAT; break;
    }
    // two W rows per thread (lstm: skip dead f-gate: [1024,3072) -> phys +1024)
    int gj0 = j0 + mrow, gj1 = j0 + 64 + mrow;
    int jp0 = lstm ? (gj0 + (gj0 >= 1024 ? 1024 : 0)) : gj0;
    int jp1 = lstm ? (gj1 + (gj1 >= 1024 ? 1024 : 0)) : gj1;
    const float* wp0 = W + (size_t)jp0 * K;
    const float* wp1 = W + (size_t)jp1 * K;
    bool v0 = gj0 < J, v1 = gj1 < J;

    int warp = tid >> 5, lane = tid & 31;
    int mw = warp * 8;            // 8 warps x 8 m-rows = 64
    int j4 = lane * 4;
    u64 acc[8][2] = {};

    auto load_x = [&](int kg) -> float4 {
        float4 xv;
        if (mode == M_SP2) {
            float4 w1 = *(const float4*)(P.W_sp1 + kg);
            float4 b1 = *(const float4*)(P.b_sp1 + kg);
            xv.x = fmaxf(spd * w1.x + b1.x, 0.f);
            xv.y = fmaxf(spd * w1.y + b1.y, 0.f);
            xv.z = fmaxf(spd * w1.z + b1.z, 0.f);
            xv.w = fmaxf(spd * w1.w + b1.w, 0.f);
        } else if (mode == M_P1) {
            xv = (kg < 80) ? *(const float4*)(xrow + kg)
                           : *(const float4*)(P.spkr + mg * 64 + (kg - 80));
        } else if (mode == M_P2) {
            float4 bb = *(const float4*)(P.b_p1 + kg);
            float4 pa = __ldcg((const float4*)(g_p1_parts + (size_t)mg * 512 + kg));
            float4 pb = __ldcg((const float4*)(g_p1_parts + (size_t)(N_B + mg) * 512 + kg));
            xv.x = fmaxf(bb.x + pa.x + pb.x, 0.f);
            xv.y = fmaxf(bb.y + pa.y + pb.y, 0.f);
            xv.z = fmaxf(bb.z + pa.z + pb.z, 0.f);
            xv.w = fmaxf(bb.w + pa.w + pb.w, 0.f);
        } else if (mode == M_L0 && kg < 256) {
            float4 a4 = *(const float4*)(P.b_p2 + kg);
            #pragma unroll
            for (int s2 = 0; s2 < S_P2; s2++) {
                float4 pp = __ldcg((const float4*)(g_p2_parts + (size_t)(s2 * N_B + mg) * 256 + kg));
                a4.x += pp.x; a4.y += pp.y; a4.z += pp.z; a4.w += pp.w;
            }
            xv.x = fmaxf(a4.x, 0.f); xv.y = fmaxf(a4.y, 0.f);
            xv.z = fmaxf(a4.z, 0.f); xv.w = fmaxf(a4.w, 0.f);
        } else if (mode == M_L0 || mode == M_L1 || mode == M_OUT) {
            xv = __ldcg((const float4*)(xrow + kg));
        } else {
            xv = *(const float4*)(xrow + kg);
        }
        return xv;
    };

    float4 xv = load_x(kbeg + kc);
    float4 wv0 = v0 ? *(const float4*)(wp0 + kbeg + kc) : make_float4(0, 0, 0, 0);
    float4 wv1 = v1 ? *(const float4*)(wp1 + kbeg + kc) : make_float4(0, 0, 0, 0);

    int buf = 0;
    for (int i = 0; i < nsl; i++) {
        // duplicated X store: [kk][2m],[2m+1] both = x
        *(float2*)&Xs[buf][kc + 0][2 * mrow] = make_float2(xv.x, xv.x);
        *(float2*)&Xs[buf][kc + 1][2 * mrow] = make_float2(xv.y, xv.y);
        *(float2*)&Xs[buf][kc + 2][2 * mrow] = make_float2(xv.z, xv.z);
        *(float2*)&Xs[buf][kc + 3][2 * mrow] = make_float2(xv.w, xv.w);
        Ws[buf][kc + 0][mrow] = wv0.x; Ws[buf][kc + 1][mrow] = wv0.y;
        Ws[buf][kc + 2][mrow] = wv0.z; Ws[buf][kc + 3][mrow] = wv0.w;
        Ws[buf][kc + 0][64 + mrow] = wv1.x; Ws[buf][kc + 1][64 + mrow] = wv1.y;
        Ws[buf][kc + 2][64 + mrow] = wv1.z; Ws[buf][kc + 3][64 + mrow] = wv1.w;
        __syncthreads();

        if (i + 1 < nsl) {    // prefetch next slice into registers
            int kg = kbeg + (i + 1) * 16 + kc;
            xv  = load_x(kg);
            wv0 = v0 ? *(const float4*)(wp0 + kg) : make_float4(0, 0, 0, 0);
            wv1 = v1 ? *(const float4*)(wp1 + kg) : make_float4(0, 0, 0, 0);
        }

        #pragma unroll
        for (int kk = 0; kk < 16; kk++) {
            ulonglong2 x01 = *(const ulonglong2*)&Xs[buf][kk][2 * mw];       // dup(m0),dup(m1)
            ulonglong2 x23 = *(const ulonglong2*)&Xs[buf][kk][2 * mw + 4];
            ulonglong2 x45 = *(const ulonglong2*)&Xs[buf][kk][2 * mw + 8];
            ulonglong2 x67 = *(const ulonglong2*)&Xs[buf][kk][2 * mw + 12];
            ulonglong2 wj  = *(const ulonglong2*)&Ws[buf][kk][j4];           // (j0,j1),(j2,j3)
            FMA2(acc[0][0], x01.x, wj.x); FMA2(acc[0][1], x01.x, wj.y);
            FMA2(acc[1][0], x01.y, wj.x); FMA2(acc[1][1], x01.y, wj.y);
            FMA2(acc[2][0], x23.x, wj.x); FMA2(acc[2][1], x23.x, wj.y);
            FMA2(acc[3][0], x23.y, wj.x); FMA2(acc[3][1], x23.y, wj.y);
            FMA2(acc[4][0], x45.x, wj.x); FMA2(acc[4][1], x45.x, wj.y);
            FMA2(acc[5][0], x45.y, wj.x); FMA2(acc[5][1], x45.y, wj.y);
            FMA2(acc[6][0], x67.x, wj.x); FMA2(acc[6][1], x67.x, wj.y);
            FMA2(acc[7][0], x67.y, wj.x); FMA2(acc[7][1], x67.y, wj.y);
        }
        buf ^= 1;
    }

    // ---- epilogue: per thread 8 rows, 4 consecutive j -> one float4/row ----
    int jg = j0 + j4;
    if (jg < J) {
        #pragma unroll
        for (int m = 0; m < 8; m++) {
            float4 v;
            UNPK(v.x, v.y, acc[m][0]);
            UNPK(v.z, v.w, acc[m][1]);
            int r = m0 + mw + m;
            switch (mode) {
                case M_ATT:
                    *(float4*)(g_att_parts + ((size_t)s * 640 + r) * ATT + jg) = v;
                    break;
                case M_P1:
                    *(float4*)(g_p1_parts + ((size_t)s * N_B + r) * 512 + jg) = v;
                    break;
                case M_SP2:
                    *(float4*)(g_sp2_parts + ((size_t)s * N_B + r) * 512 + jg) = v;
                    break;
                case M_SB: {
                    float4 a;
                    a.x = v.x / (1.f + fabsf(v.x)); a.y = v.y / (1.f + fabsf(v.y));
                    a.z = v.z / (1.f + fabsf(v.z)); a.w = v.w / (1.f + fabsf(v.w));
                    *(float4*)(g_sb + r * ATT + jg) = a;
                } break;
                case M_P2:
                    *(float4*)(g_p2_parts + ((size_t)s * N_B + r) * 256 + jg) = v;
                    break;
                case M_OUT:
                    *(float4*)(g_out_parts + ((size_t)s * N_B + r) * OUT_J + jg) = v;
                    break;
                default:   // L0 / L1
                    *(float4*)(g_lstm_parts + ((size_t)s * N_B + r) * G3 + jg) = v;
                    break;
            }
        }
    }
}

// ---------------------------------------------------------------------------
__device__ void att_finish_dev(int n, const Ptrs& P)
{
    __shared__ float red[80];
    __shared__ float logit_s[NWIN];
    __shared__ float att_s[NWIN];

    int a = threadIdx.x;          // 256
    int warp = a >> 5, lane = a & 31;

    float sb    = __ldcg(&g_sb[n * ATT + a]);
    float spw   = P.speed[n] * P.W_speed_att[a];
    float wproj = P.W_proj[a];
    float be    = P.b_enc[a];

    float v[NWIN];
    #pragma unroll
    for (int t = 0; t < NWIN; t++) {
        float dot = be;
        #pragma unroll
        for (int s = 0; s < S_ATT; s++)
            dot += __ldcg(&g_att_parts[((size_t)s * 640 + n * 10 + t) * ATT + a]);
        float eb = dot / (1.f + fabsf(dot));
        float e  = eb + sb + P.conv_prev[a * 31 + (15 - t)] + spw;
        v[t] = tanhf(e) * wproj;
    }
    #pragma unroll
    for (int t = 0; t < NWIN; t++) {
        #pragma unroll
        for (int o = 16; o > 0; o >>= 1)
            v[t] += __shfl_xor_sync(0xffffffffu, v[t], o);
    }
    if (lane == 0) {
        #pragma unroll
        for (int t = 0; t < NWIN; t++) red[warp * NWIN + t] = v[t];
    }
    __syncthreads();
    if (a < NWIN) {
        float s = 0.f;
        #pragma unroll
        for (int w = 0; w < 8; w++) s += red[w * NWIN + a];
        logit_s[a] = s + P.b_proj[0];
    }
    __syncthreads();
    if (a == 0) {
        int len1 = max(P.lengths[n], 1) - 1;
        int hi = min(9, len1);
        float m = -1e30f;
        for (int t = 0; t <= hi; t++) m = fmaxf(m, logit_s[t]);
        float ss = 0.f;
        for (int t = 0; t < NWIN; t++) {
            float w = (t <= hi) ? expf(logit_s[t] - m) : 0.f;
            att_s[t] = w; ss += w;
        }
        float inv = 1.f / fmaxf(ss, 1e-12f);
        for (int t = 0; t < NWIN; t++) att_s[t] *= inv;
    }
    __syncthreads();

    for (int e = a; e < ENC; e += 256) {
        float spv = P.b_sp2[e];
        #pragma unroll
        for (int s = 0; s < S_SP2; s++)
            spv += __ldcg(&g_sp2_parts[((size_t)s * N_B + n) * 512 + e]);
        float c = tanhf(spv);
        #pragma unroll
        for (int t = 0; t < NWIN; t++)
            c += att_s[t] * P.input_enc[((size_t)n * T_ENC + t) * ENC + e];
        g_inlstm[n * IN_LSTM + 256 + e] = c;
        g_dec[(size_t)n * DECCAT + H4 + e] = c;
        if (P.write_ctx) P.ctx_out[n * ENC + e] = c;
    }
    if (a < 64) g_inlstm[n * IN_LSTM + 768 + a] = P.spkr[n * 64 + a];
}

// ---------------------------------------------------------------------------
__device__ void act_dev(int layer, const Ptrs& P)
{
    const float* bih = layer ? P.bih1 : P.bih0;
    const float* bhh = layer ? P.bhh1 : P.bhh0;
    int idx = blockIdx.x * NTHR + threadIdx.x;
    if (idx < N_B * 256) {
        int n = idx >> 8, u4 = (idx & 255) * 4;
        float gi[4], gg[4], go[4];
        {
            float4 a = *(const float4*)(bih + u4);
            float4 b = *(const float4*)(bhh + u4);
            gi[0] = a.x + b.x; gi[1] = a.y + b.y; gi[2] = a.z + b.z; gi[3] = a.w + b.w;
            a = *(const float4*)(bih + 2048 + u4);
            b = *(const float4*)(bhh + 2048 + u4);
            gg[0] = a.x + b.x; gg[1] = a.y + b.y; gg[2] = a.z + b.z; gg[3] = a.w + b.w;
            a = *(const float4*)(bih + 3072 + u4);
            b = *(const float4*)(bhh + 3072 + u4);
            go[0] = a.x + b.x; go[1] = a.y + b.y; go[2] = a.z + b.z; go[3] = a.w + b.w;
        }
        #pragma unroll
        for (int s = 0; s < S_L; s++) {
            const float* p = g_lstm_parts + ((size_t)s * N_B + n) * G3;
            float4 a = __ldcg((const float4*)(p + u4));
            float4 b = __ldcg((const float4*)(p + 1024 + u4));
            float4 c = __ldcg((const float4*)(p + 2048 + u4));
            gi[0] += a.x; gi[1] += a.y; gi[2] += a.z; gi[3] += a.w;
            gg[0] += b.x; gg[1] += b.y; gg[2] += b.z; gg[3] += b.w;
            go[0] += c.x; go[1] += c.y; go[2] += c.z; go[3] += c.w;
        }
        float4 h;
        float* hp = &h.x;
        #pragma unroll
        for (int q = 0; q < 4; q++) {
            float c = sigm(gi[q]) * tanhf(gg[q]);
            hp[q] = sigm(go[q]) * tanhf(c);
        }
        if (layer == 0) *(float4*)(g_h1 + n * H4 + u4) = h;
        else            *(float4*)(g_dec + (size_t)n * DECCAT + u4) = h;
    }
}

// ---------------------------------------------------------------------------
__global__ void __launch_bounds__(NTHR, 1) fused_k(Ptrs P)
{
    __shared__ __align__(16) float Xs[2][16][136];
    __shared__ __align__(16) float Ws[2][16][132];

    unsigned s0 = 0;
    if (threadIdx.x == 0) s0 = g_sense;
    int b = blockIdx.x;

    // ---- stage A: ATT(120) + P1(8) + SP2(16) + SB(2) = 146 tasks ----
    if (b < 146) {
        int mode, jt, s = 0, mt = 0;
        if (b < 120)      { mode = M_ATT; jt = b & 1; int r = b >> 1; s = r % 6; mt = r / 6; }
        else if (b < 128) { int t = b - 120; mode = M_P1;  jt = t & 3; s = t >> 2; }
        else if (b < 144) { int t = b - 128; mode = M_SP2; jt = t & 3; s = t >> 2; }
        else              { mode = M_SB;  jt = b - 144; }
        gemm_tile(mode, jt, s, mt, P, Xs, Ws);
    }
    gbar(s0 + 1);

    // ---- stage B: att_finish(64) + P2 GEMM(16) ----
    if (b < 64) att_finish_dev(b, P);
    else if (b < 80) { int t = b - 64; gemm_tile(M_P2, t & 1, t >> 1, 0, P, Xs, Ws); }
    gbar(s0 + 2);

    // ---- stage C: LSTM0 GEMM (24 jt x 6 s = 144); prenet2 act in loader ----
    if (b < 144) gemm_tile(M_L0, b % 24, b / 24, 0, P, Xs, Ws);
    gbar(s0 + 3);

    // ---- stage D: LSTM0 activation ----
    act_dev(0, P);
    gbar(s0 + 4);

    // ---- stage E: LSTM1 GEMM ----
    if (b < 144) gemm_tile(M_L1, b % 24, b / 24, 0, P, Xs, Ws);
    gbar(s0 + 5);

    // ---- stage F: LSTM1 activation ----
    act_dev(1, P);
    gbar(s0 + 6);

    // ---- stage G: output GEMM (2 jt x 32 s = 64) ----
    if (b < 64) gemm_tile(M_OUT, b & 1, b >> 1, 0, P, Xs, Ws);
    gbar(s0 + 7);

    // ---- stage H: output reduction ----
    int gt = b * NTHR + threadIdx.x;
    if (gt < N_B * OUT_J) {
        int n = gt / OUT_J, j = gt - n * OUT_J;
        float a = P.b_out[j];
        #pragma unroll
        for (int s = 0; s < S_OUT; s++)
            a += __ldcg(&g_out_parts[((size_t)s * N_B + n) * OUT_J + j]);
        P.out[n * OUT_J + j] = a;
    }
}

// ---------------------------------------------------------------------------
extern "C" void kernel_launch(void* const* d_in, const int* in_sizes, int n_in,
                              void* d_out, int out_size)
{
    Ptrs P;
    P.input_enc   = (const float*)d_in[0];
    P.input_dec   = (const float*)d_in[1];
    P.spkr        = (const float*)d_in[2];
    P.lengths     = (const int*)  d_in[3];
    P.speed       = (const float*)d_in[4];
    P.W_enc       = (const float*)d_in[5];
    P.b_enc       = (const float*)d_in[6];
    P.W_spkr      = (const float*)d_in[7];
    P.conv_prev   = (const float*)d_in[8];
    P.W_speed_att = (const float*)d_in[9];
    P.W_proj      = (const float*)d_in[10];
    P.b_proj      = (const float*)d_in[11];
    P.W_sp1       = (const float*)d_in[12];
    P.b_sp1       = (const float*)d_in[13];
    P.W_sp2       = (const float*)d_in[14];
    P.b_sp2       = (const float*)d_in[15];
    P.W_p1        = (const float*)d_in[16];
    P.b_p1        = (const float*)d_in[17];
    P.W_p2        = (const float*)d_in[18];
    P.b_p2        = (const float*)d_in[19];
    P.Wih0        = (const float*)d_in[20];
    P.bih0        = (const float*)d_in[22];
    P.bhh0        = (const float*)d_in[23];
    P.Wih1        = (const float*)d_in[24];
    P.bih1        = (const float*)d_in[26];
    P.bhh1        = (const float*)d_in[27];
    P.W_out       = (const float*)d_in[28];
    P.b_out       = (const float*)d_in[29];

    float* out = (float*)d_out;
    P.out = out;
    P.write_ctx = (out_size >= N_B * 2 * 80 + N_B * ENC) ? 1 : 0;
    P.ctx_out = out + N_B * 2 * 80;

    fused_k<<<GRID, NTHR>>>(P);
}

// round 13
// speedup vs baseline: 1.5943x; 1.5943x over previous
#include <cuda_runtime.h>
#include <math.h>
#include <stddef.h>

// ---------------------------------------------------------------------------
// AttnDecoderRNN2 single step, algebraically reduced (validated):
//  * attention window always t in [0,9]; softmax max cancels in L1 norm
//  * zero LSTM state -> Whh unused, f-gate dead (i,g,o rows only: J=3072)
// Round 10: pipe-balanced inner loop. 256 thr, 8m x 4j per thread, X stored
// DUPLICATED (broadcast LDS, 1 cyc) so per kk: 4 bcast + 1 W LDS.128 + 16
// FMA2, no MOVs. Crossbar/slice = fma floor = 1024 cyc; issue 672/SMSP.
// Round-5 stage structure (7 barriers), monotonic 2-level barrier.
// ---------------------------------------------------------------------------

#define GRID    148
#define NTHR    256
#define N_B     64
#define T_ENC   2000
#define ENC     512
#define ATT     256
#define H4      1024
#define G3      3072
#define IN_LSTM 832
#define DECCAT  1536
#define NWIN    10
#define OUT_J   160

#define S_ATT 6
#define S_SP2 4
#define S_P2  8
#define S_L   6
#define S_OUT 32
#define NSUB  16

typedef unsigned long long u64;

// scratch (device globals; allocation forbidden)
__device__ __align__(16) float g_att_parts[S_ATT * 640 * ATT];
__device__ __align__(16) float g_p1_parts [2 * N_B * 512];
__device__ __align__(16) float g_sp2_parts[S_SP2 * N_B * 512];
__device__ __align__(16) float g_p2_parts [S_P2 * N_B * 256];
__device__ __align__(16) float g_sb       [N_B * ATT];
__device__ __align__(16) float g_lstm_parts[S_L * N_B * G3];
__device__ __align__(16) float g_out_parts[S_OUT * N_B * OUT_J];
__device__ __align__(16) float g_inlstm   [N_B * IN_LSTM];
__device__ __align__(16) float g_h1       [N_B * H4];
__device__ __align__(16) float g_dec      [N_B * DECCAT];    // [h2 | context]

// monotonic two-level grid barrier
__device__ unsigned g_cnt_sub[NSUB * 32];   // padded 128B apart
__device__ unsigned g_cnt_top = 0;
__device__ volatile unsigned g_sense = 0;

struct Ptrs {
    const float *input_enc, *input_dec, *spkr, *speed;
    const float *W_enc, *b_enc, *W_spkr, *conv_prev, *W_speed_att, *W_proj, *b_proj;
    const float *W_sp1, *b_sp1, *W_sp2, *b_sp2;
    const float *W_p1, *b_p1, *W_p2, *b_p2;
    const float *Wih0, *bih0, *bhh0, *Wih1, *bih1, *bhh1, *W_out, *b_out;
    const int *lengths;
    float *out, *ctx_out;
    int write_ctx;
};

__device__ __forceinline__ float sigm(float x) { return 1.f / (1.f + expf(-x)); }

#define FMA2(d, a, b) asm("fma.rn.f32x2 %0,%1,%2,%0;" : "+l"(d) : "l"(a), "l"(b))
#define UNPK(lo, hi, v) asm("mov.b64 {%0,%1},%2;" : "=f"(lo), "=f"(hi) : "l"(v))

enum { M_ATT = 0, M_P1, M_SP2, M_SB, M_P2, M_L0, M_L1, M_OUT };

// ---------------------------------------------------------------------------
__device__ __forceinline__ void gbar(unsigned target)
{
    __syncthreads();
    if (threadIdx.x == 0) {
        __threadfence();
        unsigned sub = blockIdx.x & (NSUB - 1);
        unsigned subcnt = (GRID / NSUB) + ((sub < (GRID & (NSUB - 1))) ? 1u : 0u);
        if (atomicAdd(&g_cnt_sub[sub * 32], 1u) == target * subcnt - 1u) {
            if (atomicAdd(&g_cnt_top, 1u) == target * NSUB - 1u) {
                __threadfence();
                g_sense = target;
            }
        }
        while (g_sense < target) __nanosleep(20);
        __threadfence();
    }
    __syncthreads();
}

// ---------------------------------------------------------------------------
// double-buffered GEMM tile, 256 threads. Tile 64m x 128j x chunk-k.
// X duplicated in smem: Xs[kk][2m]=Xs[kk][2m+1]=x(m). Per-thread 8m x 4j.
// Inner per kk: 4 broadcast LDS.128 (X) + 1 LDS.128 (W) + 16 FMA2.
// ---------------------------------------------------------------------------
__device__ __noinline__ void gemm_tile(int mode, int jt, int s, int mt,
                                       const Ptrs& P,
                                       float (*Xs)[16][136], float (*Ws)[16][132])
{
    int K, chunk, J;
    const float* W;
    switch (mode) {
        case M_ATT: K = 512;  chunk = 96;  J = 256;   W = P.W_enc;  break;
        case M_P1:  K = 144;  chunk = 80;  J = 512;   W = P.W_p1;   break;
        case M_SP2: K = 256;  chunk = 64;  J = 512;   W = P.W_sp2;  break;
        case M_SB:  K = 64;   chunk = 64;  J = 256;   W = P.W_spkr; break;
        case M_P2:  K = 512;  chunk = 64;  J = 256;   W = P.W_p2;   break;
        case M_L0:  K = 832;  chunk = 144; J = G3;    W = P.Wih0;   break;
        case M_L1:  K = 1024; chunk = 176; J = G3;    W = P.Wih1;   break;
        default:    K = 1536; chunk = 48;  J = OUT_J; W = P.W_out;  break;
    }
    int lstm = (mode == M_L0 || mode == M_L1);
    int j0 = jt * 128, m0 = mt * 64;
    int kbeg = s * chunk;
    int kend = min(K, kbeg + chunk);
    int nsl  = (kend - kbeg) >> 4;

    int tid  = threadIdx.x;
    int mrow = tid >> 2;          // 0..63
    int kc   = (tid & 3) * 4;
    int mg   = m0 + mrow;

    const float* xrow = 0; float spd = 0.f;
    switch (mode) {
        case M_ATT: { int n = mg / 10; int t = mg - n * 10;
                      xrow = P.input_enc + ((size_t)n * T_ENC + t) * ENC; } break;
        case M_P1:  xrow = P.input_dec + mg * 80; break;
        case M_SP2: spd = P.speed[mg]; break;
        case M_SB:  xrow = P.spkr + mg * 64; break;
        case M_P2:  break;   // from p1 partials
        case M_L0:  xrow = g_inlstm + mg * IN_LSTM; break;
        case M_L1:  xrow = g_h1 + (size_t)mg * H4; break;
        default:    xrow = g_dec + (size_t)mg * DECCAT; break;
    }
    // two W rows per thread (lstm: skip dead f-gate: [1024,3072) -> phys +1024)
    int gj0 = j0 + mrow, gj1 = j0 + 64 + mrow;
    int jp0 = lstm ? (gj0 + (gj0 >= 1024 ? 1024 : 0)) : gj0;
    int jp1 = lstm ? (gj1 + (gj1 >= 1024 ? 1024 : 0)) : gj1;
    const float* wp0 = W + (size_t)jp0 * K;
    const float* wp1 = W + (size_t)jp1 * K;
    bool v0 = gj0 < J, v1 = gj1 < J;

    int warp = tid >> 5, lane = tid & 31;
    int mw = warp * 8;            // 8 warps x 8 m-rows = 64
    int j4 = lane * 4;
    u64 acc[8][2] = {};

    auto load_x = [&](int kg) -> float4 {
        float4 xv;
        if (mode == M_SP2) {
            float4 w1 = *(const float4*)(P.W_sp1 + kg);
            float4 b1 = *(const float4*)(P.b_sp1 + kg);
            xv.x = fmaxf(spd * w1.x + b1.x, 0.f);
            xv.y = fmaxf(spd * w1.y + b1.y, 0.f);
            xv.z = fmaxf(spd * w1.z + b1.z, 0.f);
            xv.w = fmaxf(spd * w1.w + b1.w, 0.f);
        } else if (mode == M_P1) {
            xv = (kg < 80) ? *(const float4*)(xrow + kg)
                           : *(const float4*)(P.spkr + mg * 64 + (kg - 80));
        } else if (mode == M_P2) {
            float4 bb = *(const float4*)(P.b_p1 + kg);
            float4 pa = __ldcg((const float4*)(g_p1_parts + (size_t)mg * 512 + kg));
            float4 pb = __ldcg((const float4*)(g_p1_parts + (size_t)(N_B + mg) * 512 + kg));
            xv.x = fmaxf(bb.x + pa.x + pb.x, 0.f);
            xv.y = fmaxf(bb.y + pa.y + pb.y, 0.f);
            xv.z = fmaxf(bb.z + pa.z + pb.z, 0.f);
            xv.w = fmaxf(bb.w + pa.w + pb.w, 0.f);
        } else if (mode == M_L0 && kg < 256) {
            float4 a4 = *(const float4*)(P.b_p2 + kg);
            #pragma unroll
            for (int s2 = 0; s2 < S_P2; s2++) {
                float4 pp = __ldcg((const float4*)(g_p2_parts + (size_t)(s2 * N_B + mg) * 256 + kg));
                a4.x += pp.x; a4.y += pp.y; a4.z += pp.z; a4.w += pp.w;
            }
            xv.x = fmaxf(a4.x, 0.f); xv.y = fmaxf(a4.y, 0.f);
            xv.z = fmaxf(a4.z, 0.f); xv.w = fmaxf(a4.w, 0.f);
        } else if (mode == M_L0 || mode == M_L1 || mode == M_OUT) {
            xv = __ldcg((const float4*)(xrow + kg));
        } else {
            xv = *(const float4*)(xrow + kg);
        }
        return xv;
    };

    float4 xv = load_x(kbeg + kc);
    float4 wv0 = v0 ? *(const float4*)(wp0 + kbeg + kc) : make_float4(0, 0, 0, 0);
    float4 wv1 = v1 ? *(const float4*)(wp1 + kbeg + kc) : make_float4(0, 0, 0, 0);

    int buf = 0;
    for (int i = 0; i < nsl; i++) {
        // duplicated X store: [kk][2m],[2m+1] both = x
        *(float2*)&Xs[buf][kc + 0][2 * mrow] = make_float2(xv.x, xv.x);
        *(float2*)&Xs[buf][kc + 1][2 * mrow] = make_float2(xv.y, xv.y);
        *(float2*)&Xs[buf][kc + 2][2 * mrow] = make_float2(xv.z, xv.z);
        *(float2*)&Xs[buf][kc + 3][2 * mrow] = make_float2(xv.w, xv.w);
        Ws[buf][kc + 0][mrow] = wv0.x; Ws[buf][kc + 1][mrow] = wv0.y;
        Ws[buf][kc + 2][mrow] = wv0.z; Ws[buf][kc + 3][mrow] = wv0.w;
        Ws[buf][kc + 0][64 + mrow] = wv1.x; Ws[buf][kc + 1][64 + mrow] = wv1.y;
        Ws[buf][kc + 2][64 + mrow] = wv1.z; Ws[buf][kc + 3][64 + mrow] = wv1.w;
        __syncthreads();

        if (i + 1 < nsl) {    // prefetch next slice into registers
            int kg = kbeg + (i + 1) * 16 + kc;
            xv  = load_x(kg);
            wv0 = v0 ? *(const float4*)(wp0 + kg) : make_float4(0, 0, 0, 0);
            wv1 = v1 ? *(const float4*)(wp1 + kg) : make_float4(0, 0, 0, 0);
        }

        #pragma unroll
        for (int kk = 0; kk < 16; kk++) {
            ulonglong2 x01 = *(const ulonglong2*)&Xs[buf][kk][2 * mw];       // dup(m0),dup(m1)
            ulonglong2 x23 = *(const ulonglong2*)&Xs[buf][kk][2 * mw + 4];
            ulonglong2 x45 = *(const ulonglong2*)&Xs[buf][kk][2 * mw + 8];
            ulonglong2 x67 = *(const ulonglong2*)&Xs[buf][kk][2 * mw + 12];
            ulonglong2 wj  = *(const ulonglong2*)&Ws[buf][kk][j4];           // (j0,j1),(j2,j3)
            FMA2(acc[0][0], x01.x, wj.x); FMA2(acc[0][1], x01.x, wj.y);
            FMA2(acc[1][0], x01.y, wj.x); FMA2(acc[1][1], x01.y, wj.y);
            FMA2(acc[2][0], x23.x, wj.x); FMA2(acc[2][1], x23.x, wj.y);
            FMA2(acc[3][0], x23.y, wj.x); FMA2(acc[3][1], x23.y, wj.y);
            FMA2(acc[4][0], x45.x, wj.x); FMA2(acc[4][1], x45.x, wj.y);
            FMA2(acc[5][0], x45.y, wj.x); FMA2(acc[5][1], x45.y, wj.y);
            FMA2(acc[6][0], x67.x, wj.x); FMA2(acc[6][1], x67.x, wj.y);
            FMA2(acc[7][0], x67.y, wj.x); FMA2(acc[7][1], x67.y, wj.y);
        }
        buf ^= 1;
    }

    // ---- epilogue: per thread 8 rows, 4 consecutive j -> one float4/row ----
    int jg = j0 + j4;
    if (jg < J) {
        #pragma unroll
        for (int m = 0; m < 8; m++) {
            float4 v;
            UNPK(v.x, v.y, acc[m][0]);
            UNPK(v.z, v.w, acc[m][1]);
            int r = m0 + mw + m;
            switch (mode) {
                case M_ATT:
                    *(float4*)(g_att_parts + ((size_t)s * 640 + r) * ATT + jg) = v;
                    break;
                case M_P1:
                    *(float4*)(g_p1_parts + ((size_t)s * N_B + r) * 512 + jg) = v;
                    break;
                case M_SP2:
                    *(float4*)(g_sp2_parts + ((size_t)s * N_B + r) * 512 + jg) = v;
                    break;
                case M_SB: {
                    float4 a;
                    a.x = v.x / (1.f + fabsf(v.x)); a.y = v.y / (1.f + fabsf(v.y));
                    a.z = v.z / (1.f + fabsf(v.z)); a.w = v.w / (1.f + fabsf(v.w));
                    *(float4*)(g_sb + r * ATT + jg) = a;
                } break;
                case M_P2:
                    *(float4*)(g_p2_parts + ((size_t)s * N_B + r) * 256 + jg) = v;
                    break;
                case M_OUT:
                    *(float4*)(g_out_parts + ((size_t)s * N_B + r) * OUT_J + jg) = v;
                    break;
                default:   // L0 / L1
                    *(float4*)(g_lstm_parts + ((size_t)s * N_B + r) * G3 + jg) = v;
                    break;
            }
        }
    }
}

// ---------------------------------------------------------------------------
__device__ void att_finish_dev(int n, const Ptrs& P)
{
    __shared__ float red[80];
    __shared__ float logit_s[NWIN];
    __shared__ float att_s[NWIN];

    int a = threadIdx.x;          // 256
    int warp = a >> 5, lane = a & 31;

    float sb    = __ldcg(&g_sb[n * ATT + a]);
    float spw   = P.speed[n] * P.W_speed_att[a];
    float wproj = P.W_proj[a];
    float be    = P.b_enc[a];

    float v[NWIN];
    #pragma unroll
    for (int t = 0; t < NWIN; t++) {
        float dot = be;
        #pragma unroll
        for (int s = 0; s < S_ATT; s++)
            dot += __ldcg(&g_att_parts[((size_t)s * 640 + n * 10 + t) * ATT + a]);
        float eb = dot / (1.f + fabsf(dot));
        float e  = eb + sb + P.conv_prev[a * 31 + (15 - t)] + spw;
        v[t] = tanhf(e) * wproj;
    }
    #pragma unroll
    for (int t = 0; t < NWIN; t++) {
        #pragma unroll
        for (int o = 16; o > 0; o >>= 1)
            v[t] += __shfl_xor_sync(0xffffffffu, v[t], o);
    }
    if (lane == 0) {
        #pragma unroll
        for (int t = 0; t < NWIN; t++) red[warp * NWIN + t] = v[t];
    }
    __syncthreads();
    if (a < NWIN) {
        float s = 0.f;
        #pragma unroll
        for (int w = 0; w < 8; w++) s += red[w * NWIN + a];
        logit_s[a] = s + P.b_proj[0];
    }
    __syncthreads();
    if (a == 0) {
        int len1 = max(P.lengths[n], 1) - 1;
        int hi = min(9, len1);
        float m = -1e30f;
        for (int t = 0; t <= hi; t++) m = fmaxf(m, logit_s[t]);
        float ss = 0.f;
        for (int t = 0; t < NWIN; t++) {
            float w = (t <= hi) ? expf(logit_s[t] - m) : 0.f;
            att_s[t] = w; ss += w;
        }
        float inv = 1.f / fmaxf(ss, 1e-12f);
        for (int t = 0; t < NWIN; t++) att_s[t] *= inv;
    }
    __syncthreads();

    for (int e = a; e < ENC; e += 256) {
        float spv = P.b_sp2[e];
        #pragma unroll
        for (int s = 0; s < S_SP2; s++)
            spv += __ldcg(&g_sp2_parts[((size_t)s * N_B + n) * 512 + e]);
        float c = tanhf(spv);
        #pragma unroll
        for (int t = 0; t < NWIN; t++)
            c += att_s[t] * P.input_enc[((size_t)n * T_ENC + t) * ENC + e];
        g_inlstm[n * IN_LSTM + 256 + e] = c;
        g_dec[(size_t)n * DECCAT + H4 + e] = c;
        if (P.write_ctx) P.ctx_out[n * ENC + e] = c;
    }
    if (a < 64) g_inlstm[n * IN_LSTM + 768 + a] = P.spkr[n * 64 + a];
}

// ---------------------------------------------------------------------------
__device__ void act_dev(int layer, const Ptrs& P)
{
    const float* bih = layer ? P.bih1 : P.bih0;
    const float* bhh = layer ? P.bhh1 : P.bhh0;
    int idx = blockIdx.x * NTHR + threadIdx.x;
    if (idx < N_B * 256) {
        int n = idx >> 8, u4 = (idx & 255) * 4;
        float gi[4], gg[4], go[4];
        {
            float4 a = *(const float4*)(bih + u4);
            float4 b = *(const float4*)(bhh + u4);
            gi[0] = a.x + b.x; gi[1] = a.y + b.y; gi[2] = a.z + b.z; gi[3] = a.w + b.w;
            a = *(const float4*)(bih + 2048 + u4);
            b = *(const float4*)(bhh + 2048 + u4);
            gg[0] = a.x + b.x; gg[1] = a.y + b.y; gg[2] = a.z + b.z; gg[3] = a.w + b.w;
            a = *(const float4*)(bih + 3072 + u4);
            b = *(const float4*)(bhh + 3072 + u4);
            go[0] = a.x + b.x; go[1] = a.y + b.y; go[2] = a.z + b.z; go[3] = a.w + b.w;
        }
        #pragma unroll
        for (int s = 0; s < S_L; s++) {
            const float* p = g_lstm_parts + ((size_t)s * N_B + n) * G3;
            float4 a = __ldcg((const float4*)(p + u4));
            float4 b = __ldcg((const float4*)(p + 1024 + u4));
            float4 c = __ldcg((const float4*)(p + 2048 + u4));
            gi[0] += a.x; gi[1] += a.y; gi[2] += a.z; gi[3] += a.w;
            gg[0] += b.x; gg[1] += b.y; gg[2] += b.z; gg[3] += b.w;
            go[0] += c.x; go[1] += c.y; go[2] += c.z; go[3] += c.w;
        }
        float4 h;
        float* hp = &h.x;
        #pragma unroll
        for (int q = 0; q < 4; q++) {
            float c = sigm(gi[q]) * tanhf(gg[q]);
            hp[q] = sigm(go[q]) * tanhf(c);
        }
        if (layer == 0) *(float4*)(g_h1 + n * H4 + u4) = h;
        else            *(float4*)(g_dec + (size_t)n * DECCAT + u4) = h;
    }
}

// ---------------------------------------------------------------------------
__global__ void __launch_bounds__(NTHR, 1) fused_k(Ptrs P)
{
    __shared__ __align__(16) float Xs[2][16][136];
    __shared__ __align__(16) float Ws[2][16][132];

    unsigned s0 = 0;
    if (threadIdx.x == 0) s0 = g_sense;
    int b = blockIdx.x;

    // ---- stage A: ATT(120) + P1(8) + SP2(16) + SB(2) = 146 tasks ----
    if (b < 146) {
        int mode, jt, s = 0, mt = 0;
        if (b < 120)      { mode = M_ATT; jt = b & 1; int r = b >> 1; s = r % 6; mt = r / 6; }
        else if (b < 128) { int t = b - 120; mode = M_P1;  jt = t & 3; s = t >> 2; }
        else if (b < 144) { int t = b - 128; mode = M_SP2; jt = t & 3; s = t >> 2; }
        else              { mode = M_SB;  jt = b - 144; }
        gemm_tile(mode, jt, s, mt, P, Xs, Ws);
    }
    gbar(s0 + 1);

    // ---- stage B: att_finish(64) + P2 GEMM(16) ----
    if (b < 64) att_finish_dev(b, P);
    else if (b < 80) { int t = b - 64; gemm_tile(M_P2, t & 1, t >> 1, 0, P, Xs, Ws); }
    gbar(s0 + 2);

    // ---- stage C: LSTM0 GEMM (24 jt x 6 s = 144); prenet2 act in loader ----
    if (b < 144) gemm_tile(M_L0, b % 24, b / 24, 0, P, Xs, Ws);
    gbar(s0 + 3);

    // ---- stage D: LSTM0 activation ----
    act_dev(0, P);
    gbar(s0 + 4);

    // ---- stage E: LSTM1 GEMM ----
    if (b < 144) gemm_tile(M_L1, b % 24, b / 24, 0, P, Xs, Ws);
    gbar(s0 + 5);

    // ---- stage F: LSTM1 activation ----
    act_dev(1, P);
    gbar(s0 + 6);

    // ---- stage G: output GEMM (2 jt x 32 s = 64) ----
    if (b < 64) gemm_tile(M_OUT, b & 1, b >> 1, 0, P, Xs, Ws);
    gbar(s0 + 7);

    // ---- stage H: output reduction ----
    int gt = b * NTHR + threadIdx.x;
    if (gt < N_B * OUT_J) {
        int n = gt / OUT_J, j = gt - n * OUT_J;
        float a = P.b_out[j];
        #pragma unroll
        for (int s = 0; s < S_OUT; s++)
            a += __ldcg(&g_out_parts[((size_t)s * N_B + n) * OUT_J + j]);
        P.out[n * OUT_J + j] = a;
    }
}

// ---------------------------------------------------------------------------
extern "C" void kernel_launch(void* const* d_in, const int* in_sizes, int n_in,
                              void* d_out, int out_size)
{
    Ptrs P;
    P.input_enc   = (const float*)d_in[0];
    P.input_dec   = (const float*)d_in[1];
    P.spkr        = (const float*)d_in[2];
    P.lengths     = (const int*)  d_in[3];
    P.speed       = (const float*)d_in[4];
    P.W_enc       = (const float*)d_in[5];
    P.b_enc       = (const float*)d_in[6];
    P.W_spkr      = (const float*)d_in[7];
    P.conv_prev   = (const float*)d_in[8];
    P.W_speed_att = (const float*)d_in[9];
    P.W_proj      = (const float*)d_in[10];
    P.b_proj      = (const float*)d_in[11];
    P.W_sp1       = (const float*)d_in[12];
    P.b_sp1       = (const float*)d_in[13];
    P.W_sp2       = (const float*)d_in[14];
    P.b_sp2       = (const float*)d_in[15];
    P.W_p1        = (const float*)d_in[16];
    P.b_p1        = (const float*)d_in[17];
    P.W_p2        = (const float*)d_in[18];
    P.b_p2        = (const float*)d_in[19];
    P.Wih0        = (const float*)d_in[20];
    P.bih0        = (const float*)d_in[22];
    P.bhh0        = (const float*)d_in[23];
    P.Wih1        = (const float*)d_in[24];
    P.bih1        = (const float*)d_in[26];
    P.bhh1        = (const float*)d_in[27];
    P.W_out       = (const float*)d_in[28];
    P.b_out       = (const float*)d_in[29];

    float* out = (float*)d_out;
    P.out = out;
    P.write_ctx = (out_size >= N_B * 2 * 80 + N_B * ENC) ? 1 : 0;
    P.ctx_out = out + N_B * 2 * 80;

    fused_k<<<GRID, NTHR>>>(P);
}